// round 6
// baseline (speedup 1.0000x reference)
#include <cuda_runtime.h>
#include <cuda_bf16.h>
#include <cstdint>

// ---------------------------------------------------------------------------
// ProxyNCALoss on GB300 — HMMA path (ptxas stage targets sm_103: no tcgen05).
//   loss_b = d_pos[b] + log( exp(-xsq_b - 1) * (S_b - 32) - exp(-d_pos_b) )
// GEMM M=1024, N=100032 (1563 x 64), K=128, bf16 mma.sync.
// R6: B fragments persist in registers across all 8 M-iterations (LDSM traffic
// 320 -> 128 B/MMA; attacks the measured smem-BW floor).
// ---------------------------------------------------------------------------

#define C_CLS 100000
#define D_DIM 128
#define B_ROWS 1024

constexpr int BM = 128;
constexpr int BN = 64;
constexpr int NTILES = (C_CLS + BN - 1) / BN;   // 1563
constexpr int N_PADS = NTILES * BN - C_CLS;     // 32
constexpr int M_ITERS = B_ROWS / BM;            // 8

constexpr int LDS = 136;                        // bf16 elems per smem row
constexpr int A_TILE_B = BM * LDS * 2;          // 34816
constexpr int B_TILE_B = BN * LDS * 2;          // 17408
constexpr int SMEM_B_OFF = 2 * A_TILE_B;        // 69632
constexpr int SMEM_TOTAL = SMEM_B_OFF + B_TILE_B;  // 87040 (2 CTAs/SM)

// ------------------------- device scratch ----------------------------------
__device__ __nv_bfloat16 g_X[B_ROWS * D_DIM];
__device__ float g_partA[(size_t)B_ROWS * NTILES];   // [b][tile], cols 0-31
__device__ float g_partB[(size_t)B_ROWS * NTILES];   // [b][tile], cols 32-63
__device__ float g_dpos[B_ROWS];
__device__ float g_xsq[B_ROWS];
__device__ float g_loss[B_ROWS];
__device__ int   g_cnt;

// ------------------------- helpers -----------------------------------------
__device__ __forceinline__ float warp_sum(float v) {
#pragma unroll
    for (int m = 16; m > 0; m >>= 1) v += __shfl_xor_sync(0xFFFFFFFFu, v, m);
    return v;
}
__device__ __forceinline__ void cp_async16(uint32_t dst, const void* src) {
    asm volatile("cp.async.cg.shared.global [%0], [%1], 16;" :: "r"(dst), "l"(src));
}
#define CP_COMMIT() asm volatile("cp.async.commit_group;" ::: "memory")
#define CP_WAIT0()  asm volatile("cp.async.wait_group 0;" ::: "memory")

#define LDSM_X4(r0, r1, r2, r3, addr) \
    asm volatile("ldmatrix.sync.aligned.m8n8.x4.shared.b16 {%0,%1,%2,%3}, [%4];\n" \
                 : "=r"(r0), "=r"(r1), "=r"(r2), "=r"(r3) : "r"(addr))

#define MMA16816(acc, a0, a1, a2, a3, b0, b1) \
    asm volatile("mma.sync.aligned.m16n8k16.row.col.f32.bf16.bf16.f32 " \
                 "{%0,%1,%2,%3}, {%4,%5,%6,%7}, {%8,%9}, {%0,%1,%2,%3};\n" \
                 : "+f"((acc)[0]), "+f"((acc)[1]), "+f"((acc)[2]), "+f"((acc)[3]) \
                 : "r"(a0), "r"(a1), "r"(a2), "r"(a3), "r"(b0), "r"(b1))

// ------------------------- fused pre-kernel ---------------------------------
__global__ void pre_kernel(const float* __restrict__ xs,
                           const int* __restrict__ ys32,
                           const float* __restrict__ proxies) {
    if (blockIdx.x == 0 && threadIdx.x == 0) g_cnt = 0;   // reset reduce counter

    int b    = (blockIdx.x * blockDim.x + threadIdx.x) >> 5;
    int lane = threadIdx.x & 31;
    if (b >= B_ROWS) return;

    // int64-vs-int32 label detection: odd 32-bit words of the first 32 labels
    // are all zero iff int64.
    int probe = ys32[2 * lane + 1];
    bool is64 = (__ballot_sync(0xFFFFFFFFu, probe != 0) == 0u);
    int y = is64 ? ys32[2 * b] : ys32[b];

    float4 xv = reinterpret_cast<const float4*>(xs + (size_t)b * D_DIM)[lane];
    float4 pv = reinterpret_cast<const float4*>(proxies + (size_t)y * D_DIM)[lane];

    __nv_bfloat162 lo = __floats2bfloat162_rn(xv.x, xv.y);
    __nv_bfloat162 hi = __floats2bfloat162_rn(xv.z, xv.w);
    uint2 u;
    u.x = *reinterpret_cast<uint32_t*>(&lo);
    u.y = *reinterpret_cast<uint32_t*>(&hi);
    reinterpret_cast<uint2*>(g_X + (size_t)b * D_DIM)[lane] = u;

    float xsq = xv.x*xv.x + xv.y*xv.y + xv.z*xv.z + xv.w*xv.w;
    float psq = pv.x*pv.x + pv.y*pv.y + pv.z*pv.z + pv.w*pv.w;
    float xp  = xv.x*pv.x + xv.y*pv.y + xv.z*pv.z + xv.w*pv.w;
    xsq = warp_sum(xsq); psq = warp_sum(psq); xp = warp_sum(xp);
    if (lane == 0) {
        float norm = fmaxf(sqrtf(psq), 1e-12f);
        g_dpos[b] = xsq + 1.0f - 2.0f * xp / norm;
        g_xsq[b]  = xsq;
    }
}

// ------------------------- GEMM + exp row-sum -------------------------------
__global__ __launch_bounds__(256, 2) void gemm_kernel(const float* __restrict__ proxies) {
    extern __shared__ __align__(16) char smem[];
    __nv_bfloat16* sB = reinterpret_cast<__nv_bfloat16*>(smem + SMEM_B_OFF);
    const uint32_t sbase = (uint32_t)__cvta_generic_to_shared(smem);

    const int tid  = threadIdx.x;
    const int wid  = tid >> 5;
    const int lane = tid & 31;
    const int nt    = blockIdx.x;
    const int nbase = nt * BN;

    // ---- start A tile 0 load immediately ----
    {
        const char* gA = reinterpret_cast<const char*>(g_X);
#pragma unroll
        for (int j = 0; j < 8; j++) {
            int idx = tid + 256 * j;
            int r = idx >> 4, c8 = idx & 15;
            cp_async16(sbase + r * (LDS * 2) + c8 * 16, gA + r * 256 + c8 * 16);
        }
        CP_COMMIT();
    }

    // ---- B tile: batched loads (MLP=8), L2-normalize, bf16, into SMEM ----
    {
        const int r0 = wid * 8;
        float4 v[8];
#pragma unroll
        for (int i = 0; i < 8; i++) {
            const int gr = nbase + r0 + i;
            if (gr < C_CLS) v[i] = reinterpret_cast<const float4*>(proxies + (size_t)gr * D_DIM)[lane];
            else            v[i] = make_float4(0.f, 0.f, 0.f, 0.f);
        }
#pragma unroll
        for (int i = 0; i < 8; i++) {
            const int gr = nbase + r0 + i;
            float sq = warp_sum(v[i].x*v[i].x + v[i].y*v[i].y + v[i].z*v[i].z + v[i].w*v[i].w);
            float rn = rsqrtf(fmaxf(sq, 1e-24f));
            if (gr >= C_CLS) rn = 0.0f;
            __nv_bfloat162 lo = __floats2bfloat162_rn(v[i].x * rn, v[i].y * rn);
            __nv_bfloat162 hi = __floats2bfloat162_rn(v[i].z * rn, v[i].w * rn);
            uint2 u;
            u.x = *reinterpret_cast<uint32_t*>(&lo);
            u.y = *reinterpret_cast<uint32_t*>(&hi);
            *reinterpret_cast<uint2*>(&sB[(r0 + i) * LDS + lane * 4]) = u;
        }
    }
    CP_WAIT0();
    __syncthreads();      // A0 complete+visible, B ready

    // 8 warps: 4 (M) x 2 (N); warp tile 32 rows x 32 cols per M-iter
    const int mrow  = (wid >> 1) * 32;
    const int nwarp = wid & 1;
    const int ncb   = nwarp * 32;
    float* gpart = (nwarp ? g_partB : g_partA);

    const int aLane   = (lane & 15);
    const int aColOff = (lane >> 4) * 8;
    const int bRowOff = (lane & 7) + ((lane >> 4) << 3);
    const int bColOff = ((lane >> 3) & 1) * 8;

    // ---- load B fragments ONCE into registers (persist across all M-iters) --
    // breg[g][k][0..3]: colgroup g (16 cols), k-step k (16 k)
    uint32_t breg[2][8][4];
#pragma unroll
    for (int g = 0; g < 2; g++)
#pragma unroll
        for (int k = 0; k < 8; k++) {
            uint32_t addrB = (uint32_t)__cvta_generic_to_shared(
                &sB[(ncb + g * 16 + bRowOff) * LDS + k * 16 + bColOff]);
            LDSM_X4(breg[g][k][0], breg[g][k][1], breg[g][k][2], breg[g][k][3], addrB);
        }

#pragma unroll 1
    for (int it = 0; it < M_ITERS; it++) {
        const int buf = it & 1;
        // prefetch A(it+1) into buf^1 — safe after previous iter's trailing sync
        if (it + 1 < M_ITERS) {
            const char* gA = reinterpret_cast<const char*>(g_X) + (size_t)(it + 1) * BM * D_DIM * 2;
            const uint32_t dbase = sbase + (buf ^ 1) * A_TILE_B;
#pragma unroll
            for (int j = 0; j < 8; j++) {
                int idx = tid + 256 * j;
                int r = idx >> 4, c8 = idx & 15;
                cp_async16(dbase + r * (LDS * 2) + c8 * 16, gA + r * 256 + c8 * 16);
            }
            CP_COMMIT();
        }

        const __nv_bfloat16* sA = reinterpret_cast<const __nv_bfloat16*>(smem + buf * A_TILE_B);

        float acc[2][4][4];     // [mf][nf][quad]
#pragma unroll
        for (int mf = 0; mf < 2; mf++)
#pragma unroll
            for (int nf = 0; nf < 4; nf++)
#pragma unroll
                for (int j = 0; j < 4; j++) acc[mf][nf][j] = 0.0f;

#pragma unroll
        for (int k = 0; k < 8; k++) {
            const int kk = k * 16;
            uint32_t a[2][4];
#pragma unroll
            for (int mf = 0; mf < 2; mf++) {
                uint32_t addrA = (uint32_t)__cvta_generic_to_shared(
                    &sA[(mrow + mf * 16 + aLane) * LDS + kk + aColOff]);
                LDSM_X4(a[mf][0], a[mf][1], a[mf][2], a[mf][3], addrA);
            }
#pragma unroll
            for (int mf = 0; mf < 2; mf++)
#pragma unroll
                for (int g = 0; g < 2; g++) {
                    MMA16816(acc[mf][2 * g],     a[mf][0], a[mf][1], a[mf][2], a[mf][3],
                             breg[g][k][0], breg[g][k][1]);
                    MMA16816(acc[mf][2 * g + 1], a[mf][0], a[mf][1], a[mf][2], a[mf][3],
                             breg[g][k][2], breg[g][k][3]);
                }
        }

        // ---- epilogue: exp(2*dot) row sums over this warp's 32 cols ----
#pragma unroll
        for (int mf = 0; mf < 2; mf++) {
            float s0 = 0.0f, s1 = 0.0f;
#pragma unroll
            for (int nf = 0; nf < 4; nf++) {
                s0 += __expf(2.0f * acc[mf][nf][0]) + __expf(2.0f * acc[mf][nf][1]);
                s1 += __expf(2.0f * acc[mf][nf][2]) + __expf(2.0f * acc[mf][nf][3]);
            }
            s0 += __shfl_xor_sync(0xFFFFFFFFu, s0, 1);
            s0 += __shfl_xor_sync(0xFFFFFFFFu, s0, 2);
            s1 += __shfl_xor_sync(0xFFFFFFFFu, s1, 1);
            s1 += __shfl_xor_sync(0xFFFFFFFFu, s1, 2);
            if ((lane & 3) == 0) {
                int r = it * BM + mrow + mf * 16 + (lane >> 2);
                gpart[(size_t)r * NTILES + nt]       = s0;
                gpart[(size_t)(r + 8) * NTILES + nt] = s1;
            }
        }

        CP_WAIT0();        // A(it+1) landed (overlapped with k-loop + epilogue)
        __syncthreads();   // single barrier: visibility + buffer ownership
    }
}

// ------------------------- fused reduce (last-block pattern) ----------------
__global__ void reduce_kernel(float* __restrict__ out) {
    __shared__ float red[256];
    __shared__ int   is_last;
    const int b = blockIdx.x;
    const int t = threadIdx.x;
    const float* pa = g_partA + (size_t)b * NTILES;
    const float* pb = g_partB + (size_t)b * NTILES;
    float s = 0.0f;
    for (int i = t; i < NTILES; i += 256) s += pa[i] + pb[i];
    red[t] = s;
    __syncthreads();
    for (int k = 128; k > 0; k >>= 1) {
        if (t < k) red[t] += red[t + k];
        __syncthreads();
    }
    if (t == 0) {
        float S = red[0] - (float)N_PADS;     // zero-pad rows contribute exp(0)=1
        float d   = g_dpos[b];
        float xsq = g_xsq[b];
        float neg = expf(-xsq - 1.0f) * S - expf(-d);
        g_loss[b] = d + logf(neg);
        __threadfence();
        int old = atomicAdd(&g_cnt, 1);
        is_last = (old == B_ROWS - 1);
    }
    __syncthreads();
    if (is_last) {
        float v = g_loss[t] + g_loss[t + 256] + g_loss[t + 512] + g_loss[t + 768];
        red[t] = v;
        __syncthreads();
        for (int k = 128; k > 0; k >>= 1) {
            if (t < k) red[t] += red[t + k];
            __syncthreads();
        }
        if (t == 0) out[0] = red[0] * (1.0f / (float)B_ROWS);
    }
}

// ------------------------- launch -------------------------------------------
extern "C" void kernel_launch(void* const* d_in, const int* in_sizes, int n_in,
                              void* d_out, int out_size) {
    const float* xs = nullptr;
    const int*   ys = nullptr;
    const float* proxies = nullptr;
    for (int i = 0; i < n_in; i++) {
        if (in_sizes[i] == B_ROWS)              ys      = (const int*)d_in[i];
        else if (in_sizes[i] == B_ROWS * D_DIM) xs      = (const float*)d_in[i];
        else if (in_sizes[i] == C_CLS * D_DIM)  proxies = (const float*)d_in[i];
    }
    float* out = (float*)d_out;

    cudaFuncSetAttribute(gemm_kernel,
                         cudaFuncAttributeMaxDynamicSharedMemorySize, SMEM_TOTAL);

    pre_kernel<<<B_ROWS / 8, 256>>>(xs, ys, proxies);
    gemm_kernel<<<NTILES, 256, SMEM_TOTAL>>>(proxies);
    reduce_kernel<<<B_ROWS, 256>>>(out);
}

// round 7
// speedup vs baseline: 1.1244x; 1.1244x over previous
#include <cuda_runtime.h>
#include <cuda_bf16.h>
#include <cstdint>

// ---------------------------------------------------------------------------
// ProxyNCALoss on GB300 — HMMA path (ptxas stage targets sm_103: no tcgen05).
//   loss_b = d_pos[b] + log( exp(-xsq_b - 1) * (S_b - 32) - exp(-d_pos_b) )
// GEMM M=1024, N=100032 (1563 x 64), K=128, bf16 mma.sync.
// R7: FREE-RUNNING WARPS — no __syncthreads in the mainloop. Each warp owns a
// private double-buffered A tile (cp.async per-warp groups + __syncwarp), B is
// register-resident. Warps drift out of phase so MUFU (exp epilogue) overlaps
// the tensor pipe instead of serializing behind CTA-wide barriers.
// ---------------------------------------------------------------------------

#define C_CLS 100000
#define D_DIM 128
#define B_ROWS 1024

constexpr int BN = 64;
constexpr int NTILES = (C_CLS + BN - 1) / BN;   // 1563
constexpr int N_PADS = NTILES * BN - C_CLS;     // 32
constexpr int W_ITERS = 16;                     // per-warp M iterations (16 rows each)

constexpr int LDSB = 136;                       // B smem row pitch (bf16 elems)
constexpr int A_WBUF = 16 * 256;                // 16 rows x 256B (one buffer)   = 4096
constexpr int A_REGION = 2 * A_WBUF;            // per-warp double buffer        = 8192
constexpr int SMEM_B_OFF = 8 * A_REGION;        // 65536
constexpr int SMEM_TOTAL = SMEM_B_OFF + BN * LDSB * 2;   // 65536 + 17408 = 82944

// ------------------------- device scratch ----------------------------------
__device__ __nv_bfloat16 g_X[B_ROWS * D_DIM];
__device__ float g_partA[(size_t)B_ROWS * NTILES];   // [b][tile], cols 0-31
__device__ float g_partB[(size_t)B_ROWS * NTILES];   // [b][tile], cols 32-63
__device__ float g_dpos[B_ROWS];
__device__ float g_xsq[B_ROWS];
__device__ float g_loss[B_ROWS];
__device__ int   g_cnt;

// ------------------------- helpers -----------------------------------------
__device__ __forceinline__ float warp_sum(float v) {
#pragma unroll
    for (int m = 16; m > 0; m >>= 1) v += __shfl_xor_sync(0xFFFFFFFFu, v, m);
    return v;
}
__device__ __forceinline__ void cp_async16(uint32_t dst, const void* src) {
    asm volatile("cp.async.cg.shared.global [%0], [%1], 16;" :: "r"(dst), "l"(src));
}
#define CP_COMMIT() asm volatile("cp.async.commit_group;" ::: "memory")
#define CP_WAIT1()  asm volatile("cp.async.wait_group 1;" ::: "memory")
#define CP_WAIT0()  asm volatile("cp.async.wait_group 0;" ::: "memory")

#define LDSM_X4(r0, r1, r2, r3, addr) \
    asm volatile("ldmatrix.sync.aligned.m8n8.x4.shared.b16 {%0,%1,%2,%3}, [%4];\n" \
                 : "=r"(r0), "=r"(r1), "=r"(r2), "=r"(r3) : "r"(addr))

#define MMA16816(acc, a0, a1, a2, a3, b0, b1) \
    asm volatile("mma.sync.aligned.m16n8k16.row.col.f32.bf16.bf16.f32 " \
                 "{%0,%1,%2,%3}, {%4,%5,%6,%7}, {%8,%9}, {%0,%1,%2,%3};\n" \
                 : "+f"((acc)[0]), "+f"((acc)[1]), "+f"((acc)[2]), "+f"((acc)[3]) \
                 : "r"(a0), "r"(a1), "r"(a2), "r"(a3), "r"(b0), "r"(b1))

// ------------------------- fused pre-kernel ---------------------------------
__global__ void pre_kernel(const float* __restrict__ xs,
                           const int* __restrict__ ys32,
                           const float* __restrict__ proxies) {
    if (blockIdx.x == 0 && threadIdx.x == 0) g_cnt = 0;

    int b    = (blockIdx.x * blockDim.x + threadIdx.x) >> 5;
    int lane = threadIdx.x & 31;
    if (b >= B_ROWS) return;

    // int64-vs-int32 label detection: odd 32-bit words of first 32 labels all
    // zero iff int64.
    int probe = ys32[2 * lane + 1];
    bool is64 = (__ballot_sync(0xFFFFFFFFu, probe != 0) == 0u);
    int y = is64 ? ys32[2 * b] : ys32[b];

    float4 xv = reinterpret_cast<const float4*>(xs + (size_t)b * D_DIM)[lane];
    float4 pv = reinterpret_cast<const float4*>(proxies + (size_t)y * D_DIM)[lane];

    __nv_bfloat162 lo = __floats2bfloat162_rn(xv.x, xv.y);
    __nv_bfloat162 hi = __floats2bfloat162_rn(xv.z, xv.w);
    uint2 u;
    u.x = *reinterpret_cast<uint32_t*>(&lo);
    u.y = *reinterpret_cast<uint32_t*>(&hi);
    reinterpret_cast<uint2*>(g_X + (size_t)b * D_DIM)[lane] = u;

    float xsq = xv.x*xv.x + xv.y*xv.y + xv.z*xv.z + xv.w*xv.w;
    float psq = pv.x*pv.x + pv.y*pv.y + pv.z*pv.z + pv.w*pv.w;
    float xp  = xv.x*pv.x + xv.y*pv.y + xv.z*pv.z + xv.w*pv.w;
    xsq = warp_sum(xsq); psq = warp_sum(psq); xp = warp_sum(xp);
    if (lane == 0) {
        float norm = fmaxf(sqrtf(psq), 1e-12f);
        g_dpos[b] = xsq + 1.0f - 2.0f * xp / norm;
        g_xsq[b]  = xsq;
    }
}

// ------------------------- GEMM + exp row-sum -------------------------------
__global__ __launch_bounds__(256, 2) void gemm_kernel(const float* __restrict__ proxies) {
    extern __shared__ __align__(16) char smem[];
    __nv_bfloat16* sB = reinterpret_cast<__nv_bfloat16*>(smem + SMEM_B_OFF);
    const uint32_t sbase = (uint32_t)__cvta_generic_to_shared(smem);

    const int tid  = threadIdx.x;
    const int wid  = tid >> 5;
    const int lane = tid & 31;
    const int nt    = blockIdx.x;
    const int nbase = nt * BN;

    // warp's fixed M-offset within each 64-row iteration block, N-half
    const int mwarp = (wid >> 1) * 16;          // 0,16,32,48
    const int nwarp = wid & 1;
    const int ncb   = nwarp * 32;
    float* gpart = (nwarp ? g_partB : g_partA);

    const uint32_t aw_base = sbase + wid * A_REGION;   // per-warp A region

    // ---- per-warp A prefetch for iteration 0 (group 0) ----
    // tile rows: global m = it*64 + mwarp + row(0..15); 256B per row, 16 chunks.
    {
        const char* gA = reinterpret_cast<const char*>(g_X) + (size_t)(0 * 64 + mwarp) * 256;
#pragma unroll
        for (int j = 0; j < 8; j++) {
            int idx = lane + 32 * j;
            int r = idx >> 4, c = idx & 15;
            cp_async16(aw_base + r * 256 + ((c ^ (r & 7)) * 16), gA + r * 256 + c * 16);
        }
        CP_COMMIT();
    }

    // ---- B tile: batched loads (MLP=8), L2-normalize, bf16, into SMEM ----
    {
        const int r0 = wid * 8;
        float4 v[8];
#pragma unroll
        for (int i = 0; i < 8; i++) {
            const int gr = nbase + r0 + i;
            if (gr < C_CLS) v[i] = reinterpret_cast<const float4*>(proxies + (size_t)gr * D_DIM)[lane];
            else            v[i] = make_float4(0.f, 0.f, 0.f, 0.f);
        }
#pragma unroll
        for (int i = 0; i < 8; i++) {
            const int gr = nbase + r0 + i;
            float sq = warp_sum(v[i].x*v[i].x + v[i].y*v[i].y + v[i].z*v[i].z + v[i].w*v[i].w);
            float rn = rsqrtf(fmaxf(sq, 1e-24f));
            if (gr >= C_CLS) rn = 0.0f;
            __nv_bfloat162 lo = __floats2bfloat162_rn(v[i].x * rn, v[i].y * rn);
            __nv_bfloat162 hi = __floats2bfloat162_rn(v[i].z * rn, v[i].w * rn);
            uint2 u;
            u.x = *reinterpret_cast<uint32_t*>(&lo);
            u.y = *reinterpret_cast<uint32_t*>(&hi);
            *reinterpret_cast<uint2*>(&sB[(r0 + i) * LDSB + lane * 4]) = u;
        }
    }
    __syncthreads();      // ONLY CTA barrier: B tile visible to all warps

    // ---- load B fragments ONCE into registers (persist across all iters) ----
    const int bRowOff = (lane & 7) + ((lane >> 4) << 3);
    const int bColOff = ((lane >> 3) & 1) * 8;
    uint32_t breg[2][8][4];
#pragma unroll
    for (int g = 0; g < 2; g++)
#pragma unroll
        for (int k = 0; k < 8; k++) {
            uint32_t addrB = (uint32_t)__cvta_generic_to_shared(
                &sB[(ncb + g * 16 + bRowOff) * LDSB + k * 16 + bColOff]);
            LDSM_X4(breg[g][k][0], breg[g][k][1], breg[g][k][2], breg[g][k][3], addrB);
        }

    const int aRow = lane & 15;                 // local row for ldsm
    const int aChunkHalf = lane >> 4;           // 0/1: +8 elems

    // ================= free-running per-warp mainloop =================
#pragma unroll 1
    for (int it = 0; it < W_ITERS; it++) {
        const int buf = it & 1;
        if (it + 1 < W_ITERS) {   // prefetch next tile into other buffer
            const char* gA = reinterpret_cast<const char*>(g_X)
                           + (size_t)((it + 1) * 64 + mwarp) * 256;
            const uint32_t dst = aw_base + (buf ^ 1) * A_WBUF;
#pragma unroll
            for (int j = 0; j < 8; j++) {
                int idx = lane + 32 * j;
                int r = idx >> 4, c = idx & 15;
                cp_async16(dst + r * 256 + ((c ^ (r & 7)) * 16), gA + r * 256 + c * 16);
            }
            CP_COMMIT();
            CP_WAIT1();           // group(it) complete
        } else {
            CP_WAIT0();
        }
        __syncwarp();             // warp-local visibility of cp.async data

        const uint32_t abuf = aw_base + buf * A_WBUF;

        float acc[4][4];
#pragma unroll
        for (int nf = 0; nf < 4; nf++)
#pragma unroll
            for (int j = 0; j < 4; j++) acc[nf][j] = 0.0f;

#pragma unroll
        for (int k = 0; k < 8; k++) {
            const int c = 2 * k + aChunkHalf;   // 16B chunk column
            uint32_t a0, a1, a2, a3;
            uint32_t addrA = abuf + aRow * 256 + ((c ^ (aRow & 7)) * 16);
            LDSM_X4(a0, a1, a2, a3, addrA);
#pragma unroll
            for (int g = 0; g < 2; g++) {
                MMA16816(acc[2 * g],     a0, a1, a2, a3, breg[g][k][0], breg[g][k][1]);
                MMA16816(acc[2 * g + 1], a0, a1, a2, a3, breg[g][k][2], breg[g][k][3]);
            }
        }

        // ---- epilogue: exp(2*dot) row sums over this warp's 32 cols ----
        float s0 = 0.0f, s1 = 0.0f;
#pragma unroll
        for (int nf = 0; nf < 4; nf++) {
            s0 += __expf(2.0f * acc[nf][0]) + __expf(2.0f * acc[nf][1]);
            s1 += __expf(2.0f * acc[nf][2]) + __expf(2.0f * acc[nf][3]);
        }
        s0 += __shfl_xor_sync(0xFFFFFFFFu, s0, 1);
        s0 += __shfl_xor_sync(0xFFFFFFFFu, s0, 2);
        s1 += __shfl_xor_sync(0xFFFFFFFFu, s1, 1);
        s1 += __shfl_xor_sync(0xFFFFFFFFu, s1, 2);
        if ((lane & 3) == 0) {
            int r = it * 64 + mwarp + (lane >> 2);
            gpart[(size_t)r * NTILES + nt]       = s0;
            gpart[(size_t)(r + 8) * NTILES + nt] = s1;
        }
    }
}

// ------------------------- fused reduce (last-block pattern) ----------------
__global__ void reduce_kernel(float* __restrict__ out) {
    __shared__ float red[256];
    __shared__ int   is_last;
    const int b = blockIdx.x;
    const int t = threadIdx.x;
    const float* pa = g_partA + (size_t)b * NTILES;
    const float* pb = g_partB + (size_t)b * NTILES;
    float s = 0.0f;
    for (int i = t; i < NTILES; i += 256) s += pa[i] + pb[i];
    red[t] = s;
    __syncthreads();
    for (int k = 128; k > 0; k >>= 1) {
        if (t < k) red[t] += red[t + k];
        __syncthreads();
    }
    if (t == 0) {
        float S = red[0] - (float)N_PADS;     // zero-pad rows contribute exp(0)=1
        float d   = g_dpos[b];
        float xsq = g_xsq[b];
        float neg = expf(-xsq - 1.0f) * S - expf(-d);
        g_loss[b] = d + logf(neg);
        __threadfence();
        int old = atomicAdd(&g_cnt, 1);
        is_last = (old == B_ROWS - 1);
    }
    __syncthreads();
    if (is_last) {
        float v = g_loss[t] + g_loss[t + 256] + g_loss[t + 512] + g_loss[t + 768];
        red[t] = v;
        __syncthreads();
        for (int k = 128; k > 0; k >>= 1) {
            if (t < k) red[t] += red[t + k];
            __syncthreads();
        }
        if (t == 0) out[0] = red[0] * (1.0f / (float)B_ROWS);
    }
}

// ------------------------- launch -------------------------------------------
extern "C" void kernel_launch(void* const* d_in, const int* in_sizes, int n_in,
                              void* d_out, int out_size) {
    const float* xs = nullptr;
    const int*   ys = nullptr;
    const float* proxies = nullptr;
    for (int i = 0; i < n_in; i++) {
        if (in_sizes[i] == B_ROWS)              ys      = (const int*)d_in[i];
        else if (in_sizes[i] == B_ROWS * D_DIM) xs      = (const float*)d_in[i];
        else if (in_sizes[i] == C_CLS * D_DIM)  proxies = (const float*)d_in[i];
    }
    float* out = (float*)d_out;

    cudaFuncSetAttribute(gemm_kernel,
                         cudaFuncAttributeMaxDynamicSharedMemorySize, SMEM_TOTAL);

    pre_kernel<<<B_ROWS / 8, 256>>>(xs, ys, proxies);
    gemm_kernel<<<NTILES, 256, SMEM_TOTAL>>>(proxies);
    reduce_kernel<<<B_ROWS, 256>>>(out);
}